// round 16
// baseline (speedup 1.0000x reference)
#include <cuda_runtime.h>
#include <cuda_fp16.h>
#include <cstdint>

#define N_NODES 100000
#define N_EDGES 3200000
#define N_FEAT 128
#define HIDDEN 64
#define N_CLASSES 3
#define N_GRAPHS 512
#define BN_EPS 1e-5f
#define SCAN_T 1024
#define CHUNK ((N_NODES + SCAN_T - 1) / SCAN_T)
#define CSR_CAP (N_EDGES + 8 * N_NODES)

// ---- scratch: device globals, accessed ONLY by symbol in device code -------
// g_hs has one extra all-zero row (index N_NODES) used by CSR padding.
__device__ __half g_hs[(size_t)(N_NODES + 1) * HIDDEN];
__device__ float  g_h1[(size_t)N_NODES * HIDDEN];   // layer-1 output (fp32)
__device__ float  g_dinv[N_NODES];
__device__ int    g_deg[N_NODES];
__device__ int    g_row[N_NODES + 1];               // 8-aligned CSR offsets
__device__ int    g_cur[N_NODES];                   // fill cursors
__device__ int    g_csr[CSR_CAP];                   // src list (padded rows)
__device__ float  g_pool[N_GRAPHS * HIDDEN];
__device__ int    g_cnt[N_GRAPHS];
__device__ int    g_e64, g_b64;
__device__ float  g_A[2 * HIDDEN];  // BN scale per layer/channel
__device__ float  g_C[2 * HIDDEN];  // BN shift (bias folded)

__device__ __forceinline__ int b_at(const void* b, int i, int f64) {
    return f64 ? (int)((const long long*)b)[i] : ((const int*)b)[i];
}

__device__ __forceinline__ uint32_t f2tf(float v) {
    uint32_t r;
    asm("cvt.rna.tf32.f32 %0, %1;" : "=r"(r) : "f"(v));
    return r;
}

// ---- setup (PARALLEL): dtype + param classify + BN precompute --------------
__global__ void setup_kernel(const int* __restrict__ ew,
                             const int* __restrict__ bw,
                             const float* p0, const float* p1,
                             const float* p2, const float* p3,
                             const float* p4, const float* p5,
                             const float* p6, const float* p7,
                             const float* p8, const float* p9) {
    __shared__ int s_type[10];
    __shared__ const float* s_prm[10];
    const float* ps[10] = {p0, p1, p2, p3, p4, p5, p6, p7, p8, p9};
    int t = threadIdx.x;
    int w = t >> 5, lane = t & 31;

    if (w < 10) {
        const float* p = ps[w];
        float v0 = p[lane], v1 = p[lane + 32];
        int allz = __all_sync(0xffffffffu, v0 == 0.f && v1 == 0.f);
        int allo = __all_sync(0xffffffffu, v0 == 1.f && v1 == 1.f);
        int anyn = __any_sync(0xffffffffu, v0 < 0.f || v1 < 0.f);
        if (lane == 0) s_type[w] = allz ? 0 : (allo ? 1 : (anyn ? 2 : 3));
    } else if (w == 10) {
        int nz = (ew[2 * lane + 1] != 0) || (ew[2 * (lane + 32) + 1] != 0);
        int any = __any_sync(0xffffffffu, nz);
        if (lane == 0) g_e64 = !any;
    } else {
        int nz = (bw[50000 + 2 * lane + 1] != 0) ||
                 (bw[50000 + 2 * (lane + 32) + 1] != 0);
        int any = __any_sync(0xffffffffu, nz);
        if (lane == 0) g_b64 = !any;
    }
    __syncthreads();

    if (t == 0) {
        const float* bucket[4][4];
        int cnt[4] = {0, 0, 0, 0};
        for (int i = 0; i < 10; i++) {
            int ty = s_type[i];
            if (cnt[ty] < 4) bucket[ty][cnt[ty]++] = ps[i];
        }
        if (cnt[0] == 4 && cnt[1] == 2 && cnt[2] == 2 && cnt[3] == 2) {
            s_prm[0] = bucket[0][0]; s_prm[2] = bucket[0][1];
            s_prm[5] = bucket[0][2]; s_prm[7] = bucket[0][3];
            s_prm[1] = bucket[1][0]; s_prm[6] = bucket[1][1];
            s_prm[3] = bucket[2][0]; s_prm[8] = bucket[2][1];
            s_prm[4] = bucket[3][0]; s_prm[9] = bucket[3][1];
        } else {
            for (int i = 0; i < 10; i++) s_prm[i] = ps[i];
        }
    }
    __syncthreads();

    if (t < 128) {
        int L = t >> 6, c = t & 63;
        const float* b     = s_prm[L * 5 + 0];
        const float* gamma = s_prm[L * 5 + 1];
        const float* beta  = s_prm[L * 5 + 2];
        const float* rmean = s_prm[L * 5 + 3];
        const float* rvar  = s_prm[L * 5 + 4];
        float sc = gamma[c] * rsqrtf(rvar[c] + BN_EPS);
        g_A[L * 64 + c] = sc;
        g_C[L * 64 + c] = beta[c] + (b[c] - rmean[c]) * sc;
    }
}

// ---- init ------------------------------------------------------------------
__global__ void init_kernel(float* __restrict__ out, int out_size) {
    int i = blockIdx.x * blockDim.x + threadIdx.x;
    if (i < N_NODES) g_deg[i] = 0;
    if (i < (N_GRAPHS * HIDDEN) / 4)
        ((float4*)g_pool)[i] = make_float4(0.f, 0.f, 0.f, 0.f);
    if (i < N_GRAPHS) g_cnt[i] = 0;
    if (i < out_size) out[i] = 0.f;
    if (i < 16)  // zero the dummy row (index N_NODES) of g_hs
        ((uint2*)(g_hs + (size_t)N_NODES * HIDDEN))[i] = make_uint2(0u, 0u);
}

// ---- degree + pool counts fused: 4 edges/thread; low threads also do batch -
__global__ void deg_cnt_kernel(const void* __restrict__ edge,
                               const void* __restrict__ batch) {
    int t = blockIdx.x * blockDim.x + threadIdx.x;
    if (t < N_EDGES / 4) {
        if (g_e64) {
            const longlong2* d2 =
                (const longlong2*)((const long long*)edge + N_EDGES);
            longlong2 a = d2[2 * t];
            longlong2 b = d2[2 * t + 1];
            atomicAdd(&g_deg[(int)a.x], 1);
            atomicAdd(&g_deg[(int)a.y], 1);
            atomicAdd(&g_deg[(int)b.x], 1);
            atomicAdd(&g_deg[(int)b.y], 1);
        } else {
            int4 d = ((const int4*)((const int*)edge + N_EDGES))[t];
            atomicAdd(&g_deg[d.x], 1);
            atomicAdd(&g_deg[d.y], 1);
            atomicAdd(&g_deg[d.z], 1);
            atomicAdd(&g_deg[d.w], 1);
        }
    }
    if (t < N_NODES / 4) {   // batch counting (25K threads, 4 nodes each)
        if (g_b64) {
            const longlong2* b2 = (const longlong2*)batch;
            longlong2 a = b2[2 * t];
            longlong2 b = b2[2 * t + 1];
            atomicAdd(&g_cnt[(int)a.x], 1);
            atomicAdd(&g_cnt[(int)a.y], 1);
            atomicAdd(&g_cnt[(int)b.x], 1);
            atomicAdd(&g_cnt[(int)b.y], 1);
        } else {
            int4 b4 = ((const int4*)batch)[t];
            atomicAdd(&g_cnt[b4.x], 1);
            atomicAdd(&g_cnt[b4.y], 1);
            atomicAdd(&g_cnt[b4.z], 1);
            atomicAdd(&g_cnt[b4.w], 1);
        }
    }
}

// ---- dinv (after deg; before GEMM1-scaled) ---------------------------------
__global__ void dinv_kernel() {
    int i = blockIdx.x * blockDim.x + threadIdx.x;
    if (i < N_NODES) g_dinv[i] = rsqrtf((float)(g_deg[i] + 1));  // +1 self loop
}

// ---- prefix scan -> 8-aligned offsets, cursors, AND pad writes -------------
__global__ void scan_kernel() {
    __shared__ int sp[SCAN_T];
    int t = threadIdx.x;
    int lo = t * CHUNK;
    int hi = lo + CHUNK < N_NODES ? lo + CHUNK : N_NODES;
    int s = 0;
    for (int i = lo; i < hi; i++) s += (g_deg[i] + 7) & ~7;
    sp[t] = s;
    __syncthreads();
    for (int off = 1; off < SCAN_T; off <<= 1) {
        int v = (t >= off) ? sp[t - off] : 0;
        __syncthreads();
        sp[t] += v;
        __syncthreads();
    }
    int run = (t > 0) ? sp[t - 1] : 0;
    for (int i = lo; i < hi; i++) {
        g_row[i] = run;
        g_cur[i] = run;
        int d = g_deg[i];
        int aligned = (d + 7) & ~7;
        for (int j = run + d; j < run + aligned; j++)   // pad -> dummy row
            g_csr[j] = N_NODES;
        run += aligned;
    }
    if (t == SCAN_T - 1) g_row[N_NODES] = run;
}

// ---- CSR fill: 4 edges per thread ------------------------------------------
__global__ void fill_kernel(const void* __restrict__ edge) {
    int t = blockIdx.x * blockDim.x + threadIdx.x;
    if (t >= N_EDGES / 4) return;
    int s0, s1, s2, s3, d0, d1, d2, d3;
    if (g_e64) {
        const longlong2* sp2 = (const longlong2*)edge;
        const longlong2* dp2 = (const longlong2*)((const long long*)edge + N_EDGES);
        longlong2 sa = sp2[2 * t], sb = sp2[2 * t + 1];
        longlong2 da = dp2[2 * t], db = dp2[2 * t + 1];
        s0 = (int)sa.x; s1 = (int)sa.y; s2 = (int)sb.x; s3 = (int)sb.y;
        d0 = (int)da.x; d1 = (int)da.y; d2 = (int)db.x; d3 = (int)db.y;
    } else {
        int4 s4 = ((const int4*)edge)[t];
        int4 d4 = ((const int4*)((const int*)edge + N_EDGES))[t];
        s0 = s4.x; s1 = s4.y; s2 = s4.z; s3 = s4.w;
        d0 = d4.x; d1 = d4.y; d2 = d4.z; d3 = d4.w;
    }
    g_csr[atomicAdd(&g_cur[d0], 1)] = s0;
    g_csr[atomicAdd(&g_cur[d1], 1)] = s1;
    g_csr[atomicAdd(&g_cur[d2], 1)] = s2;
    g_csr[atomicAdd(&g_cur[d3], 1)] = s3;
}

// ---- TF32 tensor-core GEMM: g_hs = fp16((X@W) * dinv[row]) -----------------
// Tile 128x64, 256 threads (8 warps), mma.m16n8k8 tf32, K-chunks of 32.
template <int K, bool SRC_H1>
__global__ void gemm_tc_kernel(const float* __restrict__ X,
                               const float* __restrict__ W) {
    __shared__ uint32_t As[128 * 36];   // A chunk [row][k] tf32
    __shared__ uint32_t Wt[64 * 36];    // W chunk transposed [n][k] tf32

    const float* Xp = SRC_H1 ? (const float*)g_h1 : X;
    int t = threadIdx.x;
    int warp = t >> 5, lane = t & 31;
    int g = lane >> 2, tg = lane & 3;
    int row0 = blockIdx.x * 128;
    int R = warp * 16;

    float c[8][4];
    #pragma unroll
    for (int i = 0; i < 8; i++)
        c[i][0] = c[i][1] = c[i][2] = c[i][3] = 0.f;

    for (int kb = 0; kb < K; kb += 32) {
        __syncthreads();
        for (int i = t; i < 32 * 16; i += 256) {
            int k = i >> 4, nq = i & 15;
            float4 w4 = *(const float4*)(W + (size_t)(kb + k) * 64 + nq * 4);
            Wt[(nq * 4 + 0) * 36 + k] = f2tf(w4.x);
            Wt[(nq * 4 + 1) * 36 + k] = f2tf(w4.y);
            Wt[(nq * 4 + 2) * 36 + k] = f2tf(w4.z);
            Wt[(nq * 4 + 3) * 36 + k] = f2tf(w4.w);
        }
        for (int i = t; i < 128 * 8; i += 256) {
            int r = i >> 3, cq = i & 7;
            int gr = row0 + r;
            float4 v = make_float4(0.f, 0.f, 0.f, 0.f);
            if (gr < N_NODES)
                v = *(const float4*)(Xp + (size_t)gr * K + kb + cq * 4);
            uint32_t* dst = &As[r * 36 + cq * 4];
            dst[0] = f2tf(v.x); dst[1] = f2tf(v.y);
            dst[2] = f2tf(v.z); dst[3] = f2tf(v.w);
        }
        __syncthreads();

        #pragma unroll
        for (int ks = 0; ks < 32; ks += 8) {
            uint32_t a0 = As[(R + g) * 36 + ks + tg];
            uint32_t a1 = As[(R + g + 8) * 36 + ks + tg];
            uint32_t a2 = As[(R + g) * 36 + ks + tg + 4];
            uint32_t a3 = As[(R + g + 8) * 36 + ks + tg + 4];
            #pragma unroll
            for (int nt = 0; nt < 8; nt++) {
                uint32_t b0 = Wt[(nt * 8 + g) * 36 + ks + tg];
                uint32_t b1 = Wt[(nt * 8 + g) * 36 + ks + tg + 4];
                asm volatile(
                    "mma.sync.aligned.m16n8k8.row.col.f32.tf32.tf32.f32 "
                    "{%0,%1,%2,%3}, {%4,%5,%6,%7}, {%8,%9}, {%0,%1,%2,%3};"
                    : "+f"(c[nt][0]), "+f"(c[nt][1]),
                      "+f"(c[nt][2]), "+f"(c[nt][3])
                    : "r"(a0), "r"(a1), "r"(a2), "r"(a3), "r"(b0), "r"(b1));
            }
        }
    }

    int gr0 = row0 + R + g;
    int gr1 = gr0 + 8;
    float s0 = (gr0 < N_NODES) ? g_dinv[gr0] : 1.f;
    float s1 = (gr1 < N_NODES) ? g_dinv[gr1] : 1.f;
    #pragma unroll
    for (int nt = 0; nt < 8; nt++) {
        int col = nt * 8 + 2 * tg;
        if (gr0 < N_NODES) {
            __half2 h = __floats2half2_rn(c[nt][0] * s0, c[nt][1] * s0);
            *(uint32_t*)(g_hs + (size_t)gr0 * HIDDEN + col) = *(uint32_t*)&h;
        }
        if (gr1 < N_NODES) {
            __half2 h = __floats2half2_rn(c[nt][2] * s1, c[nt][3] * s1);
            *(uint32_t*)(g_hs + (size_t)gr1 * HIDDEN + col) = *(uint32_t*)&h;
        }
    }
}

// ---- fused gather + BN + ReLU (+ pool for layer 2) — at LTS roofline -------
template <int LAYER>
__global__ void gather_kernel(const void* __restrict__ batch) {
    int node = (blockIdx.x * blockDim.x + threadIdx.x) >> 5;
    if (node >= N_NODES) return;
    int lane = threadIdx.x & 31;
    int p = lane & 15;
    int half = lane >> 4;
    int beg = g_row[node], end = g_row[node + 1];   // both 8-aligned

    const int4* csr4 = (const int4*)g_csr;
    float4 a = make_float4(0.f, 0.f, 0.f, 0.f);

    for (int b = (beg >> 2) + half; b < (end >> 2); b += 2) {
        int4 s4 = csr4[b];
        uint2 r0 = *((const uint2*)(g_hs + (size_t)s4.x * HIDDEN) + p);
        uint2 r1 = *((const uint2*)(g_hs + (size_t)s4.y * HIDDEN) + p);
        uint2 r2 = *((const uint2*)(g_hs + (size_t)s4.z * HIDDEN) + p);
        uint2 r3 = *((const uint2*)(g_hs + (size_t)s4.w * HIDDEN) + p);
        __half2 hx0 = __hadd2(*(__half2*)&r0.x, *(__half2*)&r1.x);
        __half2 hx1 = __hadd2(*(__half2*)&r2.x, *(__half2*)&r3.x);
        __half2 hy0 = __hadd2(*(__half2*)&r0.y, *(__half2*)&r1.y);
        __half2 hy1 = __hadd2(*(__half2*)&r2.y, *(__half2*)&r3.y);
        __half2 hx = __hadd2(hx0, hx1);
        __half2 hy = __hadd2(hy0, hy1);
        float2 fx = __half22float2(hx);
        float2 fy = __half22float2(hy);
        a.x += fx.x; a.y += fx.y;
        a.z += fy.x; a.w += fy.y;
    }

    a.x += __shfl_down_sync(0xffffffffu, a.x, 16);
    a.y += __shfl_down_sync(0xffffffffu, a.y, 16);
    a.z += __shfl_down_sync(0xffffffffu, a.z, 16);
    a.w += __shfl_down_sync(0xffffffffu, a.w, 16);

    if (half == 0) {
        float di = g_dinv[node];
        uint2 raw = *((const uint2*)(g_hs + (size_t)node * HIDDEN) + p);
        float2 s01 = __half22float2(*(__half2*)&raw.x);
        float2 s23 = __half22float2(*(__half2*)&raw.y);
        float4 A = *((const float4*)(g_A + LAYER * HIDDEN) + p);
        float4 C = *((const float4*)(g_C + LAYER * HIDDEN) + p);
        float4 r;
        r.x = fmaxf(di * (a.x + s01.x) * A.x + C.x, 0.f);
        r.y = fmaxf(di * (a.y + s01.y) * A.y + C.y, 0.f);
        r.z = fmaxf(di * (a.z + s23.x) * A.z + C.z, 0.f);
        r.w = fmaxf(di * (a.w + s23.y) * A.w + C.w, 0.f);
        if (LAYER == 0) {
            *((float4*)(g_h1 + (size_t)node * HIDDEN) + p) = r;
        } else {
            int g = b_at(batch, node, g_b64);
            atomicAdd((float4*)(g_pool + (size_t)g * HIDDEN) + p, r);
        }
    }
}

// ---- classifier ------------------------------------------------------------
__global__ void classify_out_kernel(const float* __restrict__ Wc,
                                    const float* __restrict__ bc,
                                    float* __restrict__ out) {
    int g = blockIdx.x;
    int c = threadIdx.x;   // 64 threads
    float pooled = g_pool[g * HIDDEN + c] / fmaxf((float)g_cnt[g], 1.f);
    __shared__ float sp[HIDDEN];
    sp[c] = pooled;
    __syncthreads();
    if (c < N_CLASSES) {
        float o = __ldg(&bc[c]);
        for (int k = 0; k < HIDDEN; k++)
            o += sp[k] * __ldg(&Wc[k * N_CLASSES + c]);
        out[g * N_CLASSES + c] = o;
    }
}

// ---- launch ----------------------------------------------------------------
extern "C" void kernel_launch(void* const* d_in, const int* in_sizes, int n_in,
                              void* d_out, int out_size) {
    const float *x = 0, *W1 = 0, *W2 = 0, *Wc = 0, *bc = 0;
    const void *edge = 0, *batch = 0;
    const float* v64[10] = {0};
    int n64 = 0;
    for (int i = 0; i < n_in; i++) {
        switch (in_sizes[i]) {
            case 12800000: x     = (const float*)d_in[i]; break;
            case 8192:     W1    = (const float*)d_in[i]; break;
            case 4096:     W2    = (const float*)d_in[i]; break;
            case 192:      Wc    = (const float*)d_in[i]; break;
            case 3:        bc    = (const float*)d_in[i]; break;
            case 6400000:  edge  = d_in[i];               break;
            case 100000:   batch = d_in[i];               break;
            case 64: if (n64 < 10) v64[n64++] = (const float*)d_in[i]; break;
            default: break;
        }
    }
    float* out = (float*)d_out;
    const int T = 256;
    const int GB = (N_NODES + 127) / 128;   // gemm blocks

    cudaStream_t s2;
    cudaStreamCreate(&s2);
    cudaEvent_t evFork, evJoin;
    cudaEventCreateWithFlags(&evFork, cudaEventDisableTiming);
    cudaEventCreateWithFlags(&evJoin, cudaEventDisableTiming);

    // main chain: setup + init + deg/cnt + dinv
    setup_kernel<<<1, 384>>>((const int*)edge, (const int*)batch,
                             v64[0], v64[1], v64[2], v64[3], v64[4],
                             v64[5], v64[6], v64[7], v64[8], v64[9]);
    init_kernel<<<(N_NODES + T - 1) / T, T>>>(out, out_size);
    deg_cnt_kernel<<<(N_EDGES / 4 + T - 1) / T, T>>>(edge, batch);
    dinv_kernel<<<(N_NODES + T - 1) / T, T>>>();

    // fork: GEMM1 (dinv-scaled) overlaps scan + fill
    cudaEventRecord(evFork, 0);
    cudaStreamWaitEvent(s2, evFork, 0);
    gemm_tc_kernel<N_FEAT, false><<<GB, T, 0, s2>>>(x, W1);
    cudaEventRecord(evJoin, s2);

    scan_kernel<<<1, SCAN_T>>>();
    fill_kernel<<<(N_EDGES / 4 + T - 1) / T, T>>>(edge);

    // join, then layer-1 gather
    cudaStreamWaitEvent(0, evJoin, 0);
    gather_kernel<0><<<(N_NODES * 32 + T - 1) / T, T>>>(batch);

    // layer 2
    gemm_tc_kernel<HIDDEN, true><<<GB, T>>>(0, W2);
    gather_kernel<1><<<(N_NODES * 32 + T - 1) / T, T>>>(batch);

    // classifier
    classify_out_kernel<<<N_GRAPHS, HIDDEN>>>(Wc, bc, out);
}

// round 17
// speedup vs baseline: 2.0124x; 2.0124x over previous
#include <cuda_runtime.h>
#include <cuda_fp16.h>
#include <cstdint>

#define N_NODES 100000
#define N_EDGES 3200000
#define N_FEAT 128
#define HIDDEN 64
#define N_CLASSES 3
#define N_GRAPHS 512
#define BN_EPS 1e-5f
#define SCAN_T 1024
#define N_TILES ((N_NODES + SCAN_T - 1) / SCAN_T)
#define CSR_CAP (N_EDGES + 8 * N_NODES)

// ---- scratch: device globals, accessed ONLY by symbol in device code -------
// g_hs has one extra all-zero row (index N_NODES) used by CSR padding.
__device__ __half g_hs[(size_t)(N_NODES + 1) * HIDDEN];
__device__ float  g_h1[(size_t)N_NODES * HIDDEN];   // layer-1 output (fp32)
__device__ float  g_dinv[N_NODES];
__device__ int    g_deg[N_NODES];
__device__ int    g_row[N_NODES + 1];               // 8-aligned CSR offsets
__device__ int    g_cur[N_NODES];                   // fill cursors
__device__ int    g_csr[CSR_CAP];                   // src list (padded rows)
__device__ float  g_pool[N_GRAPHS * HIDDEN];
__device__ int    g_cnt[N_GRAPHS];
__device__ int    g_e64, g_b64;
__device__ float  g_A[2 * HIDDEN];  // BN scale per layer/channel
__device__ float  g_C[2 * HIDDEN];  // BN shift (bias folded)

__device__ __forceinline__ int b_at(const void* b, int i, int f64) {
    return f64 ? (int)((const long long*)b)[i] : ((const int*)b)[i];
}

__device__ __forceinline__ uint32_t f2tf(float v) {
    uint32_t r;
    asm("cvt.rna.tf32.f32 %0, %1;" : "=r"(r) : "f"(v));
    return r;
}

// ---- setup (PARALLEL): dtype + param classify + BN precompute --------------
__global__ void setup_kernel(const int* __restrict__ ew,
                             const int* __restrict__ bw,
                             const float* p0, const float* p1,
                             const float* p2, const float* p3,
                             const float* p4, const float* p5,
                             const float* p6, const float* p7,
                             const float* p8, const float* p9) {
    __shared__ int s_type[10];
    __shared__ const float* s_prm[10];
    const float* ps[10] = {p0, p1, p2, p3, p4, p5, p6, p7, p8, p9};
    int t = threadIdx.x;
    int w = t >> 5, lane = t & 31;

    if (w < 10) {
        const float* p = ps[w];
        float v0 = p[lane], v1 = p[lane + 32];
        int allz = __all_sync(0xffffffffu, v0 == 0.f && v1 == 0.f);
        int allo = __all_sync(0xffffffffu, v0 == 1.f && v1 == 1.f);
        int anyn = __any_sync(0xffffffffu, v0 < 0.f || v1 < 0.f);
        if (lane == 0) s_type[w] = allz ? 0 : (allo ? 1 : (anyn ? 2 : 3));
    } else if (w == 10) {
        int nz = (ew[2 * lane + 1] != 0) || (ew[2 * (lane + 32) + 1] != 0);
        int any = __any_sync(0xffffffffu, nz);
        if (lane == 0) g_e64 = !any;
    } else {
        int nz = (bw[50000 + 2 * lane + 1] != 0) ||
                 (bw[50000 + 2 * (lane + 32) + 1] != 0);
        int any = __any_sync(0xffffffffu, nz);
        if (lane == 0) g_b64 = !any;
    }
    __syncthreads();

    if (t == 0) {
        const float* bucket[4][4];
        int cnt[4] = {0, 0, 0, 0};
        for (int i = 0; i < 10; i++) {
            int ty = s_type[i];
            if (cnt[ty] < 4) bucket[ty][cnt[ty]++] = ps[i];
        }
        if (cnt[0] == 4 && cnt[1] == 2 && cnt[2] == 2 && cnt[3] == 2) {
            s_prm[0] = bucket[0][0]; s_prm[2] = bucket[0][1];
            s_prm[5] = bucket[0][2]; s_prm[7] = bucket[0][3];
            s_prm[1] = bucket[1][0]; s_prm[6] = bucket[1][1];
            s_prm[3] = bucket[2][0]; s_prm[8] = bucket[2][1];
            s_prm[4] = bucket[3][0]; s_prm[9] = bucket[3][1];
        } else {
            for (int i = 0; i < 10; i++) s_prm[i] = ps[i];
        }
    }
    __syncthreads();

    if (t < 128) {
        int L = t >> 6, c = t & 63;
        const float* b     = s_prm[L * 5 + 0];
        const float* gamma = s_prm[L * 5 + 1];
        const float* beta  = s_prm[L * 5 + 2];
        const float* rmean = s_prm[L * 5 + 3];
        const float* rvar  = s_prm[L * 5 + 4];
        float sc = gamma[c] * rsqrtf(rvar[c] + BN_EPS);
        g_A[L * 64 + c] = sc;
        g_C[L * 64 + c] = beta[c] + (b[c] - rmean[c]) * sc;
    }
}

// ---- init ------------------------------------------------------------------
__global__ void init_kernel(float* __restrict__ out, int out_size) {
    int i = blockIdx.x * blockDim.x + threadIdx.x;
    if (i < N_NODES) g_deg[i] = 0;
    if (i < (N_GRAPHS * HIDDEN) / 4)
        ((float4*)g_pool)[i] = make_float4(0.f, 0.f, 0.f, 0.f);
    if (i < N_GRAPHS) g_cnt[i] = 0;
    if (i < out_size) out[i] = 0.f;
    if (i < 16)  // zero the dummy row (index N_NODES) of g_hs
        ((uint2*)(g_hs + (size_t)N_NODES * HIDDEN))[i] = make_uint2(0u, 0u);
}

// ---- degree + pool counts fused: 4 edges/thread; low threads also do batch -
__global__ void deg_cnt_kernel(const void* __restrict__ edge,
                               const void* __restrict__ batch) {
    int t = blockIdx.x * blockDim.x + threadIdx.x;
    if (t < N_EDGES / 4) {
        if (g_e64) {
            const longlong2* d2 =
                (const longlong2*)((const long long*)edge + N_EDGES);
            longlong2 a = d2[2 * t];
            longlong2 b = d2[2 * t + 1];
            atomicAdd(&g_deg[(int)a.x], 1);
            atomicAdd(&g_deg[(int)a.y], 1);
            atomicAdd(&g_deg[(int)b.x], 1);
            atomicAdd(&g_deg[(int)b.y], 1);
        } else {
            int4 d = ((const int4*)((const int*)edge + N_EDGES))[t];
            atomicAdd(&g_deg[d.x], 1);
            atomicAdd(&g_deg[d.y], 1);
            atomicAdd(&g_deg[d.z], 1);
            atomicAdd(&g_deg[d.w], 1);
        }
    }
    if (t < N_NODES / 4) {
        if (g_b64) {
            const longlong2* b2 = (const longlong2*)batch;
            longlong2 a = b2[2 * t];
            longlong2 b = b2[2 * t + 1];
            atomicAdd(&g_cnt[(int)a.x], 1);
            atomicAdd(&g_cnt[(int)a.y], 1);
            atomicAdd(&g_cnt[(int)b.x], 1);
            atomicAdd(&g_cnt[(int)b.y], 1);
        } else {
            int4 b4 = ((const int4*)batch)[t];
            atomicAdd(&g_cnt[b4.x], 1);
            atomicAdd(&g_cnt[b4.y], 1);
            atomicAdd(&g_cnt[b4.z], 1);
            atomicAdd(&g_cnt[b4.w], 1);
        }
    }
}

// ---- coalesced tiled scan: 98 tiles x 1024 nodes, shfl block-scan ----------
// Writes g_row, g_cur, g_dinv; g_row[N_NODES] at the end. All accesses
// coalesced (tile-contiguous), no scattered stores (pads are grid-wide).
__global__ void scan_kernel() {
    __shared__ int warp_sums[32];
    __shared__ int s_carry;
    int t = threadIdx.x;
    int wid = t >> 5, lane = t & 31;
    if (t == 0) s_carry = 0;
    __syncthreads();

    for (int tile = 0; tile < N_TILES; tile++) {
        int idx = tile * SCAN_T + t;
        int d = (idx < N_NODES) ? g_deg[idx] : 0;
        int a = (d + 7) & ~7;

        // inclusive warp scan of a
        int v = a;
        #pragma unroll
        for (int off = 1; off < 32; off <<= 1) {
            int n = __shfl_up_sync(0xffffffffu, v, off);
            if (lane >= off) v += n;
        }
        if (lane == 31) warp_sums[wid] = v;
        __syncthreads();
        if (wid == 0) {
            int w = warp_sums[lane];
            #pragma unroll
            for (int off = 1; off < 32; off <<= 1) {
                int n = __shfl_up_sync(0xffffffffu, w, off);
                if (lane >= off) w += n;
            }
            warp_sums[lane] = w;
        }
        __syncthreads();

        int carry = s_carry;
        int warp_off = (wid > 0) ? warp_sums[wid - 1] : 0;
        int excl = carry + warp_off + v - a;
        if (idx < N_NODES) {
            g_row[idx] = excl;
            g_cur[idx] = excl;
            g_dinv[idx] = rsqrtf((float)(d + 1));   // +1 self loop
        }
        int tile_total = warp_sums[31];
        __syncthreads();   // all threads have read s_carry & warp_sums
        if (t == 0) s_carry = carry + tile_total;
        __syncthreads();
    }
    if (t == 0) g_row[N_NODES] = s_carry;
}

// ---- CSR fill: 4 edges per thread ------------------------------------------
__global__ void fill_kernel(const void* __restrict__ edge) {
    int t = blockIdx.x * blockDim.x + threadIdx.x;
    if (t >= N_EDGES / 4) return;
    int s0, s1, s2, s3, d0, d1, d2, d3;
    if (g_e64) {
        const longlong2* sp2 = (const longlong2*)edge;
        const longlong2* dp2 = (const longlong2*)((const long long*)edge + N_EDGES);
        longlong2 sa = sp2[2 * t], sb = sp2[2 * t + 1];
        longlong2 da = dp2[2 * t], db = dp2[2 * t + 1];
        s0 = (int)sa.x; s1 = (int)sa.y; s2 = (int)sb.x; s3 = (int)sb.y;
        d0 = (int)da.x; d1 = (int)da.y; d2 = (int)db.x; d3 = (int)db.y;
    } else {
        int4 s4 = ((const int4*)edge)[t];
        int4 d4 = ((const int4*)((const int*)edge + N_EDGES))[t];
        s0 = s4.x; s1 = s4.y; s2 = s4.z; s3 = s4.w;
        d0 = d4.x; d1 = d4.y; d2 = d4.z; d3 = d4.w;
    }
    g_csr[atomicAdd(&g_cur[d0], 1)] = s0;
    g_csr[atomicAdd(&g_cur[d1], 1)] = s1;
    g_csr[atomicAdd(&g_cur[d2], 1)] = s2;
    g_csr[atomicAdd(&g_cur[d3], 1)] = s3;
}

// ---- pad (grid-wide): fill padded tails with the dummy zero row ------------
__global__ void pad_kernel() {
    int n = blockIdx.x * blockDim.x + threadIdx.x;
    if (n >= N_NODES) return;
    int d = g_deg[n];
    int start = g_row[n] + d;
    int end = g_row[n] + ((d + 7) & ~7);
    for (int j = start; j < end; j++) g_csr[j] = N_NODES;
}

// ---- TF32 tensor-core GEMM: g_hs = fp16((X@W) [* dinv if SCALE]) -----------
template <int K, bool SRC_H1, bool SCALE>
__global__ void gemm_tc_kernel(const float* __restrict__ X,
                               const float* __restrict__ W) {
    __shared__ uint32_t As[128 * 36];
    __shared__ uint32_t Wt[64 * 36];

    const float* Xp = SRC_H1 ? (const float*)g_h1 : X;
    int t = threadIdx.x;
    int warp = t >> 5, lane = t & 31;
    int g = lane >> 2, tg = lane & 3;
    int row0 = blockIdx.x * 128;
    int R = warp * 16;

    float c[8][4];
    #pragma unroll
    for (int i = 0; i < 8; i++)
        c[i][0] = c[i][1] = c[i][2] = c[i][3] = 0.f;

    for (int kb = 0; kb < K; kb += 32) {
        __syncthreads();
        for (int i = t; i < 32 * 16; i += 256) {
            int k = i >> 4, nq = i & 15;
            float4 w4 = *(const float4*)(W + (size_t)(kb + k) * 64 + nq * 4);
            Wt[(nq * 4 + 0) * 36 + k] = f2tf(w4.x);
            Wt[(nq * 4 + 1) * 36 + k] = f2tf(w4.y);
            Wt[(nq * 4 + 2) * 36 + k] = f2tf(w4.z);
            Wt[(nq * 4 + 3) * 36 + k] = f2tf(w4.w);
        }
        for (int i = t; i < 128 * 8; i += 256) {
            int r = i >> 3, cq = i & 7;
            int gr = row0 + r;
            float4 v = make_float4(0.f, 0.f, 0.f, 0.f);
            if (gr < N_NODES)
                v = *(const float4*)(Xp + (size_t)gr * K + kb + cq * 4);
            uint32_t* dst = &As[r * 36 + cq * 4];
            dst[0] = f2tf(v.x); dst[1] = f2tf(v.y);
            dst[2] = f2tf(v.z); dst[3] = f2tf(v.w);
        }
        __syncthreads();

        #pragma unroll
        for (int ks = 0; ks < 32; ks += 8) {
            uint32_t a0 = As[(R + g) * 36 + ks + tg];
            uint32_t a1 = As[(R + g + 8) * 36 + ks + tg];
            uint32_t a2 = As[(R + g) * 36 + ks + tg + 4];
            uint32_t a3 = As[(R + g + 8) * 36 + ks + tg + 4];
            #pragma unroll
            for (int nt = 0; nt < 8; nt++) {
                uint32_t b0 = Wt[(nt * 8 + g) * 36 + ks + tg];
                uint32_t b1 = Wt[(nt * 8 + g) * 36 + ks + tg + 4];
                asm volatile(
                    "mma.sync.aligned.m16n8k8.row.col.f32.tf32.tf32.f32 "
                    "{%0,%1,%2,%3}, {%4,%5,%6,%7}, {%8,%9}, {%0,%1,%2,%3};"
                    : "+f"(c[nt][0]), "+f"(c[nt][1]),
                      "+f"(c[nt][2]), "+f"(c[nt][3])
                    : "r"(a0), "r"(a1), "r"(a2), "r"(a3), "r"(b0), "r"(b1));
            }
        }
    }

    int gr0 = row0 + R + g;
    int gr1 = gr0 + 8;
    float s0 = 1.f, s1 = 1.f;
    if (SCALE) {
        if (gr0 < N_NODES) s0 = g_dinv[gr0];
        if (gr1 < N_NODES) s1 = g_dinv[gr1];
    }
    #pragma unroll
    for (int nt = 0; nt < 8; nt++) {
        int col = nt * 8 + 2 * tg;
        if (gr0 < N_NODES) {
            __half2 h = __floats2half2_rn(c[nt][0] * s0, c[nt][1] * s0);
            *(uint32_t*)(g_hs + (size_t)gr0 * HIDDEN + col) = *(uint32_t*)&h;
        }
        if (gr1 < N_NODES) {
            __half2 h = __floats2half2_rn(c[nt][2] * s1, c[nt][3] * s1);
            *(uint32_t*)(g_hs + (size_t)gr1 * HIDDEN + col) = *(uint32_t*)&h;
        }
    }
}

// ---- scale hs rows by dinv (layer-1; keeps GEMM1 independent of scan) ------
__global__ void scale_hs_kernel() {
    int i = blockIdx.x * blockDim.x + threadIdx.x;   // over uint4 (8 halves)
    if (i >= N_NODES * 8) return;
    float di = g_dinv[i >> 3];
    uint4 raw = ((uint4*)g_hs)[i];
    float2 f0 = __half22float2(*(__half2*)&raw.x);
    float2 f1 = __half22float2(*(__half2*)&raw.y);
    float2 f2 = __half22float2(*(__half2*)&raw.z);
    float2 f3 = __half22float2(*(__half2*)&raw.w);
    __half2 h0 = __floats2half2_rn(f0.x * di, f0.y * di);
    __half2 h1 = __floats2half2_rn(f1.x * di, f1.y * di);
    __half2 h2 = __floats2half2_rn(f2.x * di, f2.y * di);
    __half2 h3 = __floats2half2_rn(f3.x * di, f3.y * di);
    ((uint4*)g_hs)[i] = make_uint4(*(unsigned*)&h0, *(unsigned*)&h1,
                                   *(unsigned*)&h2, *(unsigned*)&h3);
}

// ---- fused gather + BN + ReLU (+ pool for layer 2) — at LTS roofline -------
template <int LAYER>
__global__ void gather_kernel(const void* __restrict__ batch) {
    int node = (blockIdx.x * blockDim.x + threadIdx.x) >> 5;
    if (node >= N_NODES) return;
    int lane = threadIdx.x & 31;
    int p = lane & 15;
    int half = lane >> 4;
    int beg = g_row[node], end = g_row[node + 1];   // both 8-aligned

    const int4* csr4 = (const int4*)g_csr;
    float4 a = make_float4(0.f, 0.f, 0.f, 0.f);

    for (int b = (beg >> 2) + half; b < (end >> 2); b += 2) {
        int4 s4 = csr4[b];
        uint2 r0 = *((const uint2*)(g_hs + (size_t)s4.x * HIDDEN) + p);
        uint2 r1 = *((const uint2*)(g_hs + (size_t)s4.y * HIDDEN) + p);
        uint2 r2 = *((const uint2*)(g_hs + (size_t)s4.z * HIDDEN) + p);
        uint2 r3 = *((const uint2*)(g_hs + (size_t)s4.w * HIDDEN) + p);
        __half2 hx0 = __hadd2(*(__half2*)&r0.x, *(__half2*)&r1.x);
        __half2 hx1 = __hadd2(*(__half2*)&r2.x, *(__half2*)&r3.x);
        __half2 hy0 = __hadd2(*(__half2*)&r0.y, *(__half2*)&r1.y);
        __half2 hy1 = __hadd2(*(__half2*)&r2.y, *(__half2*)&r3.y);
        __half2 hx = __hadd2(hx0, hx1);
        __half2 hy = __hadd2(hy0, hy1);
        float2 fx = __half22float2(hx);
        float2 fy = __half22float2(hy);
        a.x += fx.x; a.y += fx.y;
        a.z += fy.x; a.w += fy.y;
    }

    a.x += __shfl_down_sync(0xffffffffu, a.x, 16);
    a.y += __shfl_down_sync(0xffffffffu, a.y, 16);
    a.z += __shfl_down_sync(0xffffffffu, a.z, 16);
    a.w += __shfl_down_sync(0xffffffffu, a.w, 16);

    if (half == 0) {
        float di = g_dinv[node];
        uint2 raw = *((const uint2*)(g_hs + (size_t)node * HIDDEN) + p);
        float2 s01 = __half22float2(*(__half2*)&raw.x);
        float2 s23 = __half22float2(*(__half2*)&raw.y);
        float4 A = *((const float4*)(g_A + LAYER * HIDDEN) + p);
        float4 C = *((const float4*)(g_C + LAYER * HIDDEN) + p);
        float4 r;
        r.x = fmaxf(di * (a.x + s01.x) * A.x + C.x, 0.f);
        r.y = fmaxf(di * (a.y + s01.y) * A.y + C.y, 0.f);
        r.z = fmaxf(di * (a.z + s23.x) * A.z + C.z, 0.f);
        r.w = fmaxf(di * (a.w + s23.y) * A.w + C.w, 0.f);
        if (LAYER == 0) {
            *((float4*)(g_h1 + (size_t)node * HIDDEN) + p) = r;
        } else {
            int g = b_at(batch, node, g_b64);
            atomicAdd((float4*)(g_pool + (size_t)g * HIDDEN) + p, r);
        }
    }
}

// ---- classifier ------------------------------------------------------------
__global__ void classify_out_kernel(const float* __restrict__ Wc,
                                    const float* __restrict__ bc,
                                    float* __restrict__ out) {
    int g = blockIdx.x;
    int c = threadIdx.x;   // 64 threads
    float pooled = g_pool[g * HIDDEN + c] / fmaxf((float)g_cnt[g], 1.f);
    __shared__ float sp[HIDDEN];
    sp[c] = pooled;
    __syncthreads();
    if (c < N_CLASSES) {
        float o = __ldg(&bc[c]);
        for (int k = 0; k < HIDDEN; k++)
            o += sp[k] * __ldg(&Wc[k * N_CLASSES + c]);
        out[g * N_CLASSES + c] = o;
    }
}

// ---- launch ----------------------------------------------------------------
extern "C" void kernel_launch(void* const* d_in, const int* in_sizes, int n_in,
                              void* d_out, int out_size) {
    const float *x = 0, *W1 = 0, *W2 = 0, *Wc = 0, *bc = 0;
    const void *edge = 0, *batch = 0;
    const float* v64[10] = {0};
    int n64 = 0;
    for (int i = 0; i < n_in; i++) {
        switch (in_sizes[i]) {
            case 12800000: x     = (const float*)d_in[i]; break;
            case 8192:     W1    = (const float*)d_in[i]; break;
            case 4096:     W2    = (const float*)d_in[i]; break;
            case 192:      Wc    = (const float*)d_in[i]; break;
            case 3:        bc    = (const float*)d_in[i]; break;
            case 6400000:  edge  = d_in[i];               break;
            case 100000:   batch = d_in[i];               break;
            case 64: if (n64 < 10) v64[n64++] = (const float*)d_in[i]; break;
            default: break;
        }
    }
    float* out = (float*)d_out;
    const int T = 256;
    const int GB = (N_NODES + 127) / 128;   // gemm blocks

    cudaStream_t s2;
    cudaStreamCreate(&s2);
    cudaEvent_t evFork, evJoin;
    cudaEventCreateWithFlags(&evFork, cudaEventDisableTiming);
    cudaEventCreateWithFlags(&evJoin, cudaEventDisableTiming);

    // fork at t=0: GEMM1 (unscaled) overlaps the whole CSR-build chain
    cudaEventRecord(evFork, 0);
    cudaStreamWaitEvent(s2, evFork, 0);
    gemm_tc_kernel<N_FEAT, false, false><<<GB, T, 0, s2>>>(x, W1);
    cudaEventRecord(evJoin, s2);

    // main chain: setup + init + deg/cnt + scan + fill + pad
    setup_kernel<<<1, 384>>>((const int*)edge, (const int*)batch,
                             v64[0], v64[1], v64[2], v64[3], v64[4],
                             v64[5], v64[6], v64[7], v64[8], v64[9]);
    init_kernel<<<(N_NODES + T - 1) / T, T>>>(out, out_size);
    deg_cnt_kernel<<<(N_EDGES / 4 + T - 1) / T, T>>>(edge, batch);
    scan_kernel<<<1, SCAN_T>>>();
    fill_kernel<<<(N_EDGES / 4 + T - 1) / T, T>>>(edge);
    pad_kernel<<<(N_NODES + T - 1) / T, T>>>();

    // join, scale hs by dinv, then layer-1 gather
    cudaStreamWaitEvent(0, evJoin, 0);
    scale_hs_kernel<<<(N_NODES * 8 + T - 1) / T, T>>>();
    gather_kernel<0><<<(N_NODES * 32 + T - 1) / T, T>>>(batch);

    // layer 2 (dinv folded into GEMM epilogue)
    gemm_tc_kernel<HIDDEN, true, true><<<GB, T>>>(0, W2);
    gather_kernel<1><<<(N_NODES * 32 + T - 1) / T, T>>>(batch);

    // classifier
    classify_out_kernel<<<N_GRAPHS, HIDDEN>>>(Wc, bc, out);
}